// round 2
// baseline (speedup 1.0000x reference)
#include <cuda_runtime.h>
#include <cuda_bf16.h>
#include <cstdint>

// ---------------------------------------------------------------------------
// Constants
// ---------------------------------------------------------------------------
constexpr int NROWS = 8192;
constexpr int DDIM  = 256;
constexpr int BM    = 128;            // Q rows per CTA
constexpr int BN    = 64;             // G rows per tile
constexpr int HALF  = NROWS / 2;      // 4096 j per CTA
constexpr int NT    = HALF / BN;      // 64 tiles
constexpr int ROWB  = DDIM * 2;       // 512 bytes per bf16 row
constexpr int TILE_BYTES = BN * ROWB; // 32768
constexpr int NBUF  = 4;

constexpr int SM_A    = 0;                           // 65536 B (A tile)
constexpr int SM_G    = BM * ROWB;                   // 65536
constexpr int SM_MBAR = SM_G + NBUF * TILE_BYTES;    // 196608
constexpr int SMEM_TOTAL = SM_MBAR + 64;

// ---------------------------------------------------------------------------
// Device scratch (no cudaMalloc allowed)
// ---------------------------------------------------------------------------
__device__ __align__(128) unsigned char g_swz[NROWS * ROWB];  // 4 MB, tile-swizzled bf16
__device__ float g_diag_arr[NROWS];
__device__ float g_pm[2 * NROWS];
__device__ float g_ps[2 * NROWS];

// ---------------------------------------------------------------------------
// PTX helpers (sm_103 baseline only: mma.sync / ldmatrix / cp.async.bulk)
// ---------------------------------------------------------------------------
__device__ __forceinline__ uint32_t smem_to_u32(const void* p) {
    uint32_t a;
    asm("{ .reg .u64 t; cvta.to.shared.u64 t, %1; cvt.u32.u64 %0, t; }" : "=r"(a) : "l"(p));
    return a;
}

#define MBARRIER_INIT(addr, count) \
    asm volatile("mbarrier.init.shared.b64 [%0], %1;" :: "r"((uint32_t)(addr)), "r"((uint32_t)(count)) : "memory")

#define MBARRIER_EXPECT_TX(addr, tx) \
    asm volatile("mbarrier.arrive.expect_tx.shared.b64 _, [%0], %1;" :: "r"((uint32_t)(addr)), "r"((uint32_t)(tx)) : "memory")

#define MBARRIER_WAIT_PARITY(addr, ph) do { \
    uint32_t _m = (uint32_t)(addr), _p = (uint32_t)(ph), _d; \
    asm volatile("{\n\t.reg .pred p;\n\t" \
        "mbarrier.try_wait.parity.acquire.cta.shared::cta.b64 p, [%1], %2;\n\t" \
        "selp.b32 %0, 1, 0, p;\n\t}" : "=r"(_d) : "r"(_m), "r"(_p) : "memory"); \
    if (!_d) { \
        asm volatile("{\n\t.reg .pred P1;\n\t" \
            "WL_%=:\n\t" \
            "mbarrier.try_wait.parity.acquire.cta.shared::cta.b64 P1, [%0], %1, 0x989680;\n\t" \
            "@P1 bra.uni WD_%=;\n\t" \
            "bra.uni WL_%=;\n\t" \
            "WD_%=:\n\t}" :: "r"(_m), "r"(_p) : "memory"); \
    } \
} while (0)

__device__ __forceinline__ void bulk_g2s(uint32_t dst, const void* src, uint32_t bytes, uint32_t mbar) {
    asm volatile(
        "cp.async.bulk.shared::cluster.global.mbarrier::complete_tx::bytes [%0], [%1], %2, [%3];"
        :: "r"(dst), "l"(src), "r"(bytes), "r"(mbar) : "memory");
}

__device__ __forceinline__ void ldsm_x4(uint32_t& r0, uint32_t& r1, uint32_t& r2, uint32_t& r3,
                                        uint32_t addr) {
    asm volatile("ldmatrix.sync.aligned.m8n8.x4.shared.b16 {%0,%1,%2,%3}, [%4];"
        : "=r"(r0), "=r"(r1), "=r"(r2), "=r"(r3) : "r"(addr));
}

__device__ __forceinline__ void mma_bf16(float* c, uint32_t a0, uint32_t a1, uint32_t a2, uint32_t a3,
                                         uint32_t b0, uint32_t b1) {
    asm volatile(
        "mma.sync.aligned.m16n8k16.row.col.f32.bf16.bf16.f32 "
        "{%0,%1,%2,%3}, {%4,%5,%6,%7}, {%8,%9}, {%0,%1,%2,%3};"
        : "+f"(c[0]), "+f"(c[1]), "+f"(c[2]), "+f"(c[3])
        : "r"(a0), "r"(a1), "r"(a2), "r"(a3), "r"(b0), "r"(b1));
}

__device__ __forceinline__ uint32_t pack_bf16(float lo, float hi) {
    uint32_t r;
    asm("cvt.rn.bf16x2.f32 %0, %1, %2;" : "=r"(r) : "f"(hi), "f"(lo));
    return r;
}

// swizzle: 16B-chunk XOR within a 64-row tile, row stride 512B
// byte(row, chunk16) = row*512 + ((chunk16 ^ (row & 7)) << 4)

// ---------------------------------------------------------------------------
// Kernel 1: G fp32 -> tile-swizzled bf16 (64-row blocks, contiguous 32KB each)
// ---------------------------------------------------------------------------
__global__ void convert_g_kernel(const float* __restrict__ g) {
    int idx = blockIdx.x * blockDim.x + threadIdx.x;   // one 16B-bf16 chunk (8 floats)
    int j = idx >> 5;          // G row
    int c = idx & 31;          // chunk16 within row
    const float4* g4 = reinterpret_cast<const float4*>(g);
    float4 v0 = g4[j * 64 + c * 2];
    float4 v1 = g4[j * 64 + c * 2 + 1];
    uint4 u;
    u.x = pack_bf16(v0.x, v0.y);
    u.y = pack_bf16(v0.z, v0.w);
    u.z = pack_bf16(v1.x, v1.y);
    u.w = pack_bf16(v1.z, v1.w);
    int blk = j >> 6, r = j & 63;
    *reinterpret_cast<uint4*>(g_swz + (size_t)blk * TILE_BYTES + r * ROWB +
                              (((c ^ (r & 7)) << 4))) = u;
}

// ---------------------------------------------------------------------------
// Kernel 2: exact fp32 diagonal
// ---------------------------------------------------------------------------
__global__ void diag_kernel(const float* __restrict__ q, const float* __restrict__ g) {
    int w = threadIdx.x >> 5, lane = threadIdx.x & 31;
    int row = blockIdx.x * 8 + w;
    const float4* qr = reinterpret_cast<const float4*>(q + (size_t)row * DDIM);
    const float4* gr = reinterpret_cast<const float4*>(g + (size_t)row * DDIM);
    float acc = 0.f;
#pragma unroll
    for (int i = 0; i < 2; i++) {
        float4 a = qr[i * 32 + lane];
        float4 b = gr[i * 32 + lane];
        acc += a.x * b.x + a.y * b.y + a.z * b.z + a.w * b.w;
    }
#pragma unroll
    for (int o = 16; o; o >>= 1) acc += __shfl_xor_sync(0xffffffffu, acc, o);
    if (lane == 0) g_diag_arr[row] = acc;
}

// ---------------------------------------------------------------------------
// Main fused kernel
// ---------------------------------------------------------------------------
__global__ void __launch_bounds__(256, 1)
fused_kernel(const float* __restrict__ q) {
    extern __shared__ char smem[];
    const uint32_t sb = smem_to_u32(smem);
    const int tid  = threadIdx.x;
    const int wid  = tid >> 5;
    const int lane = tid & 31;
    const int rb   = blockIdx.x >> 1;
    const int h    = blockIdx.x & 1;

    // ---- init mbarriers ----
    if (tid == 0) {
#pragma unroll
        for (int i = 0; i < NBUF; i++) MBARRIER_INIT(sb + SM_MBAR + i * 8, 1);
    }
    asm volatile("fence.proxy.async.shared::cta;" ::: "memory");
    __syncthreads();

    // ---- kick off first NBUF tile loads ----
    if (tid == 0) {
#pragma unroll
        for (int p = 0; p < NBUF; p++) {
            MBARRIER_EXPECT_TX(sb + SM_MBAR + p * 8, TILE_BYTES);
            bulk_g2s(sb + SM_G + p * TILE_BYTES,
                     g_swz + (size_t)(h * NT + p) * TILE_BYTES,
                     TILE_BYTES, sb + SM_MBAR + p * 8);
        }
    }

    // ---- stage A: 128 Q rows -> bf16, swizzled into smem ----
    {
        const float4* q4 = reinterpret_cast<const float4*>(q);
#pragma unroll
        for (int i = 0; i < 32; i++) {
            int idx = tid + i * 256;           // float4 index within A tile
            int r = idx >> 6, c = idx & 63;    // row, float4-chunk
            float4 v = q4[(size_t)(rb * BM + r) * 64 + c];
            uint2 u;
            u.x = pack_bf16(v.x, v.y);
            u.y = pack_bf16(v.z, v.w);
            *reinterpret_cast<uint2*>(smem + SM_A + r * ROWB +
                                      (((c >> 1) ^ (r & 7)) << 4) + (c & 1) * 8) = u;
        }
    }
    __syncthreads();

    // ---- per-lane addressing for ldmatrix ----
    const int g_row = lane >> 2;                             // accum row group
    const uint32_t a_row  = wid * 16 + ((lane >> 3) & 1) * 8 + (lane & 7);
    const uint32_t a_base = sb + SM_A + a_row * ROWB;
    const uint32_t a_x    = a_row & 7;
    const uint32_t a_hi   = lane >> 4;                       // 0/1 -> +16B (k+8)
    const uint32_t b_rowl = ((lane >> 4) << 3) + (lane & 7); // 0..15
    const uint32_t b_x    = b_rowl & 7;
    const uint32_t b_hi   = (lane >> 3) & 1;
    const uint32_t b_roff = b_rowl * ROWB;

    float mA = -__int_as_float(0x7f800000), sA = 0.f;
    float mB = -__int_as_float(0x7f800000), sB = 0.f;

    auto do_tile = [&](int t, float (&acc)[32]) {
        const int b = t & 3;
        const uint32_t mb = sb + SM_MBAR + b * 8;
        MBARRIER_WAIT_PARITY(mb, (t >> 2) & 1);
#pragma unroll
        for (int i = 0; i < 32; i++) acc[i] = 0.f;
        const uint32_t gbase = sb + SM_G + b * TILE_BYTES + b_roff;
#pragma unroll
        for (int ks = 0; ks < 16; ks++) {
            uint32_t a0, a1, a2, a3;
            ldsm_x4(a0, a1, a2, a3, a_base + ((((ks << 1) + a_hi) ^ a_x) << 4));
            const uint32_t bc = (((ks << 1) + b_hi) ^ b_x) << 4;
#pragma unroll
            for (int nb = 0; nb < 4; nb++) {
                uint32_t b0, b1, b2, b3;
                ldsm_x4(b0, b1, b2, b3, gbase + nb * (16 * ROWB) + bc);
                mma_bf16(acc + nb * 8 + 0, a0, a1, a2, a3, b0, b1);
                mma_bf16(acc + nb * 8 + 4, a0, a1, a2, a3, b2, b3);
            }
        }
        __syncthreads();   // everyone done reading buf b
        if (tid == 0 && t + NBUF < NT) {
            MBARRIER_EXPECT_TX(mb, TILE_BYTES);
            bulk_g2s(sb + SM_G + b * TILE_BYTES,
                     g_swz + (size_t)(h * NT + t + NBUF) * TILE_BYTES,
                     TILE_BYTES, mb);
        }
    };

    auto do_epi = [&](float (&acc)[32]) {
        float v0 = mA, v1 = mB;
#pragma unroll
        for (int i = 0; i < 8; i++) {
            v0 = fmaxf(v0, fmaxf(acc[i * 4 + 0], acc[i * 4 + 1]));
            v1 = fmaxf(v1, fmaxf(acc[i * 4 + 2], acc[i * 4 + 3]));
        }
        sA *= __expf(mA - v0);
        sB *= __expf(mB - v1);
        float t0 = 0.f, t1 = 0.f;
#pragma unroll
        for (int i = 0; i < 8; i++) {
            t0 += __expf(acc[i * 4 + 0] - v0) + __expf(acc[i * 4 + 1] - v0);
            t1 += __expf(acc[i * 4 + 2] - v1) + __expf(acc[i * 4 + 3] - v1);
        }
        sA += t0; sB += t1; mA = v0; mB = v1;
    };

    // ---- software-pipelined main loop: epilogue(t-1) overlaps MMA(t) ----
    float accA[32], accB[32];
    do_tile(0, accA);
    for (int tt = 1; tt < NT; tt += 2) {
        do_tile(tt, accB);
        do_epi(accA);
        if (tt + 1 < NT) {
            do_tile(tt + 1, accA);
            do_epi(accB);
        }
    }
    do_epi(accB);   // NT even: last tile (NT-1) landed in accB

    // ---- quad reduce (lanes sharing a row) + write partials ----
#pragma unroll
    for (int off = 1; off <= 2; off <<= 1) {
        float mo = __shfl_xor_sync(0xffffffffu, mA, off);
        float so = __shfl_xor_sync(0xffffffffu, sA, off);
        float M = fmaxf(mA, mo);
        sA = sA * __expf(mA - M) + so * __expf(mo - M);
        mA = M;
        mo = __shfl_xor_sync(0xffffffffu, mB, off);
        so = __shfl_xor_sync(0xffffffffu, sB, off);
        M = fmaxf(mB, mo);
        sB = sB * __expf(mB - M) + so * __expf(mo - M);
        mB = M;
    }
    if ((lane & 3) == 0) {
        int r0 = rb * BM + wid * 16 + g_row;
        g_pm[h * NROWS + r0] = mA;
        g_ps[h * NROWS + r0] = sA;
        g_pm[h * NROWS + r0 + 8] = mB;
        g_ps[h * NROWS + r0 + 8] = sB;
    }
}

// ---------------------------------------------------------------------------
// Kernel 4: merge halves, diagonal NLL, mean
// ---------------------------------------------------------------------------
__global__ void finalize_kernel(float* __restrict__ out) {
    __shared__ float red[256];
    float acc = 0.f;
    for (int i = threadIdx.x; i < NROWS; i += 256) {
        float m0 = g_pm[i], m1 = g_pm[NROWS + i];
        float s0 = g_ps[i], s1 = g_ps[NROWS + i];
        float M = fmaxf(m0, m1);
        float S = s0 * __expf(m0 - M) + s1 * __expf(m1 - M);
        float p = __expf(g_diag_arr[i] - M) / S;
        acc += -logf(p + 1e-5f);
    }
    red[threadIdx.x] = acc;
    __syncthreads();
    for (int o = 128; o; o >>= 1) {
        if (threadIdx.x < o) red[threadIdx.x] += red[threadIdx.x + o];
        __syncthreads();
    }
    if (threadIdx.x == 0) out[0] = red[0] / (float)NROWS;
}

// ---------------------------------------------------------------------------
// Launch
// ---------------------------------------------------------------------------
extern "C" void kernel_launch(void* const* d_in, const int* in_sizes, int n_in,
                              void* d_out, int out_size) {
    (void)in_sizes; (void)n_in; (void)out_size;
    const float* q = (const float*)d_in[0];
    const float* g = (const float*)d_in[1];
    float* out = (float*)d_out;

    cudaFuncSetAttribute(fused_kernel, cudaFuncAttributeMaxDynamicSharedMemorySize, SMEM_TOTAL);

    convert_g_kernel<<<(NROWS * DDIM / 8) / 256, 256>>>(g);
    diag_kernel<<<NROWS / 8, 256>>>(q, g);
    fused_kernel<<<(NROWS / BM) * 2, 256, SMEM_TOTAL>>>(q);
    finalize_kernel<<<1, 256>>>(out);
}

// round 3
// speedup vs baseline: 1.3898x; 1.3898x over previous
#include <cuda_runtime.h>
#include <cuda_bf16.h>
#include <cstdint>

// ---------------------------------------------------------------------------
// Constants
// ---------------------------------------------------------------------------
constexpr int NROWS = 8192;
constexpr int DDIM  = 256;
constexpr int BM    = 128;            // Q rows per CTA
constexpr int BN    = 64;             // G rows per tile
constexpr int NTU   = 8;              // tiles per CTA (unit)
constexpr int NCHUNK = NROWS / (BN * NTU);   // 16 column chunks per row-block
constexpr int GRID_F = (NROWS / BM) * NCHUNK; // 1024 CTAs
constexpr int ROWB  = DDIM * 2;       // 512 bytes per bf16 row
constexpr int TILE_BYTES = BN * ROWB; // 32768
constexpr int NBUF  = 4;

constexpr int SM_A    = 0;                           // 65536 B (A tile)
constexpr int SM_G    = BM * ROWB;                   // 65536
constexpr int SM_MBAR = SM_G + NBUF * TILE_BYTES;    // 196608
constexpr int SMEM_TOTAL = SM_MBAR + 64;

#define LOG2E 1.4426950408889634f

// ---------------------------------------------------------------------------
// Device scratch (no cudaMalloc allowed)
// ---------------------------------------------------------------------------
__device__ __align__(128) unsigned char g_swz[NROWS * ROWB];  // 4 MB tile-swizzled bf16
__device__ float g_diag_arr[NROWS];          // base-2-scaled exact diagonal
__device__ float g_pm[NCHUNK * NROWS];
__device__ float g_ps[NCHUNK * NROWS];
__device__ unsigned g_cnt = 0;

// ---------------------------------------------------------------------------
// PTX helpers (sm_103 baseline only)
// ---------------------------------------------------------------------------
__device__ __forceinline__ uint32_t smem_to_u32(const void* p) {
    uint32_t a;
    asm("{ .reg .u64 t; cvta.to.shared.u64 t, %1; cvt.u32.u64 %0, t; }" : "=r"(a) : "l"(p));
    return a;
}

__device__ __forceinline__ float ex2(float x) {
    float r;
    asm("ex2.approx.f32 %0, %1;" : "=f"(r) : "f"(x));
    return r;
}

#define MBARRIER_INIT(addr, count) \
    asm volatile("mbarrier.init.shared.b64 [%0], %1;" :: "r"((uint32_t)(addr)), "r"((uint32_t)(count)) : "memory")

#define MBARRIER_EXPECT_TX(addr, tx) \
    asm volatile("mbarrier.arrive.expect_tx.shared.b64 _, [%0], %1;" :: "r"((uint32_t)(addr)), "r"((uint32_t)(tx)) : "memory")

#define MBARRIER_WAIT_PARITY(addr, ph) do { \
    uint32_t _m = (uint32_t)(addr), _p = (uint32_t)(ph), _d; \
    asm volatile("{\n\t.reg .pred p;\n\t" \
        "mbarrier.try_wait.parity.acquire.cta.shared::cta.b64 p, [%1], %2;\n\t" \
        "selp.b32 %0, 1, 0, p;\n\t}" : "=r"(_d) : "r"(_m), "r"(_p) : "memory"); \
    if (!_d) { \
        asm volatile("{\n\t.reg .pred P1;\n\t" \
            "WL_%=:\n\t" \
            "mbarrier.try_wait.parity.acquire.cta.shared::cta.b64 P1, [%0], %1, 0x989680;\n\t" \
            "@P1 bra.uni WD_%=;\n\t" \
            "bra.uni WL_%=;\n\t" \
            "WD_%=:\n\t}" :: "r"(_m), "r"(_p) : "memory"); \
    } \
} while (0)

__device__ __forceinline__ void bulk_g2s(uint32_t dst, const void* src, uint32_t bytes, uint32_t mbar) {
    asm volatile(
        "cp.async.bulk.shared::cluster.global.mbarrier::complete_tx::bytes [%0], [%1], %2, [%3];"
        :: "r"(dst), "l"(src), "r"(bytes), "r"(mbar) : "memory");
}

__device__ __forceinline__ void ldsm_x4(uint32_t& r0, uint32_t& r1, uint32_t& r2, uint32_t& r3,
                                        uint32_t addr) {
    asm volatile("ldmatrix.sync.aligned.m8n8.x4.shared.b16 {%0,%1,%2,%3}, [%4];"
        : "=r"(r0), "=r"(r1), "=r"(r2), "=r"(r3) : "r"(addr));
}

__device__ __forceinline__ void mma_bf16(float* c, uint32_t a0, uint32_t a1, uint32_t a2, uint32_t a3,
                                         uint32_t b0, uint32_t b1) {
    asm volatile(
        "mma.sync.aligned.m16n8k16.row.col.f32.bf16.bf16.f32 "
        "{%0,%1,%2,%3}, {%4,%5,%6,%7}, {%8,%9}, {%0,%1,%2,%3};"
        : "+f"(c[0]), "+f"(c[1]), "+f"(c[2]), "+f"(c[3])
        : "r"(a0), "r"(a1), "r"(a2), "r"(a3), "r"(b0), "r"(b1));
}

__device__ __forceinline__ uint32_t pack_bf16(float lo, float hi) {
    uint32_t r;
    asm("cvt.rn.bf16x2.f32 %0, %1, %2;" : "=r"(r) : "f"(hi), "f"(lo));
    return r;
}

// ---------------------------------------------------------------------------
// Prep kernel: [bid<1024] G fp32 -> tile-swizzled bf16 ; [bid>=1024] exact diag
// ---------------------------------------------------------------------------
__global__ void prep_kernel(const float* __restrict__ q, const float* __restrict__ g) {
    if (blockIdx.x < 1024) {
        int idx = blockIdx.x * 256 + threadIdx.x;   // one 16B bf16 chunk (8 floats)
        int j = idx >> 5;          // G row
        int c = idx & 31;          // chunk16 within row
        const float4* g4 = reinterpret_cast<const float4*>(g);
        float4 v0 = g4[j * 64 + c * 2];
        float4 v1 = g4[j * 64 + c * 2 + 1];
        uint4 u;
        u.x = pack_bf16(v0.x, v0.y);
        u.y = pack_bf16(v0.z, v0.w);
        u.z = pack_bf16(v1.x, v1.y);
        u.w = pack_bf16(v1.z, v1.w);
        int blk = j >> 6, r = j & 63;
        *reinterpret_cast<uint4*>(g_swz + (size_t)blk * TILE_BYTES + r * ROWB +
                                  ((c ^ (r & 7)) << 4)) = u;
    } else {
        int w = threadIdx.x >> 5, lane = threadIdx.x & 31;
        int row = (blockIdx.x - 1024) * 8 + w;
        const float4* qr = reinterpret_cast<const float4*>(q + (size_t)row * DDIM);
        const float4* gr = reinterpret_cast<const float4*>(g + (size_t)row * DDIM);
        float acc = 0.f;
#pragma unroll
        for (int i = 0; i < 2; i++) {
            float4 a = qr[i * 32 + lane];
            float4 b = gr[i * 32 + lane];
            acc += a.x * b.x + a.y * b.y + a.z * b.z + a.w * b.w;
        }
#pragma unroll
        for (int o = 16; o; o >>= 1) acc += __shfl_xor_sync(0xffffffffu, acc, o);
        if (lane == 0) g_diag_arr[row] = acc * LOG2E;   // base-2 domain
    }
}

// ---------------------------------------------------------------------------
// Main fused kernel: (row-block, column-chunk) units, 8 tiles each,
// online base-2 softmax, last-CTA finalize.
// ---------------------------------------------------------------------------
__global__ void __launch_bounds__(256, 1)
fused_kernel(const float* __restrict__ q, float* __restrict__ out) {
    extern __shared__ char smem[];
    const uint32_t sb = smem_to_u32(smem);
    const int tid  = threadIdx.x;
    const int wid  = tid >> 5;
    const int lane = tid & 31;
    const int rb    = blockIdx.x >> 4;    // row block (0..63)
    const int chunk = blockIdx.x & 15;    // column chunk (0..15), 512 cols each
    const int ct0   = chunk * NTU;        // first global column-tile

    // ---- init mbarriers ----
    if (tid == 0) {
#pragma unroll
        for (int i = 0; i < NBUF; i++) MBARRIER_INIT(sb + SM_MBAR + i * 8, 1);
    }
    asm volatile("fence.proxy.async.shared::cta;" ::: "memory");
    __syncthreads();

    // ---- kick off first NBUF tile loads ----
    if (tid == 0) {
#pragma unroll
        for (int p = 0; p < NBUF; p++) {
            MBARRIER_EXPECT_TX(sb + SM_MBAR + p * 8, TILE_BYTES);
            bulk_g2s(sb + SM_G + p * TILE_BYTES,
                     g_swz + (size_t)(ct0 + p) * TILE_BYTES,
                     TILE_BYTES, sb + SM_MBAR + p * 8);
        }
    }

    // ---- stage A: 128 Q rows -> bf16 (pre-scaled by log2e), swizzled ----
    {
        const float4* q4 = reinterpret_cast<const float4*>(q);
#pragma unroll
        for (int i = 0; i < 32; i++) {
            int idx = tid + i * 256;           // float4 index within A tile
            int r = idx >> 6, c = idx & 63;    // row, float4-chunk
            float4 v = q4[(size_t)(rb * BM + r) * 64 + c];
            uint2 u;
            u.x = pack_bf16(v.x * LOG2E, v.y * LOG2E);
            u.y = pack_bf16(v.z * LOG2E, v.w * LOG2E);
            *reinterpret_cast<uint2*>(smem + SM_A + r * ROWB +
                                      (((c >> 1) ^ (r & 7)) << 4) + (c & 1) * 8) = u;
        }
    }
    __syncthreads();

    // ---- per-lane addressing for ldmatrix ----
    const int g_row = lane >> 2;
    const uint32_t a_row  = wid * 16 + ((lane >> 3) & 1) * 8 + (lane & 7);
    const uint32_t a_base = sb + SM_A + a_row * ROWB;
    const uint32_t a_x    = a_row & 7;
    const uint32_t a_hi   = lane >> 4;
    const uint32_t b_rowl = ((lane >> 4) << 3) + (lane & 7);
    const uint32_t b_x    = b_rowl & 7;
    const uint32_t b_hi   = (lane >> 3) & 1;
    const uint32_t b_roff = b_rowl * ROWB;

    float mA = -__int_as_float(0x7f800000), sA = 0.f;
    float mB = -__int_as_float(0x7f800000), sB = 0.f;

    auto do_tile = [&](int t, float (&acc)[32]) {
        const int b = t & (NBUF - 1);
        const uint32_t mb = sb + SM_MBAR + b * 8;
        MBARRIER_WAIT_PARITY(mb, (t >> 2) & 1);
#pragma unroll
        for (int i = 0; i < 32; i++) acc[i] = 0.f;
        const uint32_t gbase = sb + SM_G + b * TILE_BYTES + b_roff;
#pragma unroll
        for (int ks = 0; ks < 16; ks++) {
            uint32_t a0, a1, a2, a3;
            ldsm_x4(a0, a1, a2, a3, a_base + ((((ks << 1) + a_hi) ^ a_x) << 4));
            const uint32_t bc = (((ks << 1) + b_hi) ^ b_x) << 4;
#pragma unroll
            for (int nb = 0; nb < 4; nb++) {
                uint32_t b0, b1, b2, b3;
                ldsm_x4(b0, b1, b2, b3, gbase + nb * (16 * ROWB) + bc);
                mma_bf16(acc + nb * 8 + 0, a0, a1, a2, a3, b0, b1);
                mma_bf16(acc + nb * 8 + 4, a0, a1, a2, a3, b2, b3);
            }
        }
        __syncthreads();   // all warps done reading buf b
        if (tid == 0 && t + NBUF < NTU) {
            MBARRIER_EXPECT_TX(mb, TILE_BYTES);
            bulk_g2s(sb + SM_G + b * TILE_BYTES,
                     g_swz + (size_t)(ct0 + t + NBUF) * TILE_BYTES,
                     TILE_BYTES, mb);
        }
    };

    auto do_epi = [&](float (&acc)[32]) {
        float v0 = mA, v1 = mB;
#pragma unroll
        for (int i = 0; i < 8; i++) {
            v0 = fmaxf(v0, fmaxf(acc[i * 4 + 0], acc[i * 4 + 1]));
            v1 = fmaxf(v1, fmaxf(acc[i * 4 + 2], acc[i * 4 + 3]));
        }
        sA *= ex2(mA - v0);
        sB *= ex2(mB - v1);
        float t0 = 0.f, t1 = 0.f;
#pragma unroll
        for (int i = 0; i < 8; i++) {
            t0 += ex2(acc[i * 4 + 0] - v0) + ex2(acc[i * 4 + 1] - v0);
            t1 += ex2(acc[i * 4 + 2] - v1) + ex2(acc[i * 4 + 3] - v1);
        }
        sA += t0; sB += t1; mA = v0; mB = v1;
    };

    // ---- software-pipelined main loop ----
    float accA[32], accB[32];
    do_tile(0, accA);
    for (int tt = 1; tt < NTU; tt += 2) {
        do_tile(tt, accB);
        do_epi(accA);
        if (tt + 1 < NTU) {
            do_tile(tt + 1, accA);
            do_epi(accB);
        }
    }
    do_epi(accB);   // NTU even: last tile landed in accB

    // ---- quad reduce + write partials ----
#pragma unroll
    for (int off = 1; off <= 2; off <<= 1) {
        float mo = __shfl_xor_sync(0xffffffffu, mA, off);
        float so = __shfl_xor_sync(0xffffffffu, sA, off);
        float M = fmaxf(mA, mo);
        sA = sA * ex2(mA - M) + so * ex2(mo - M);
        mA = M;
        mo = __shfl_xor_sync(0xffffffffu, mB, off);
        so = __shfl_xor_sync(0xffffffffu, sB, off);
        M = fmaxf(mB, mo);
        sB = sB * ex2(mB - M) + so * ex2(mo - M);
        mB = M;
    }
    if ((lane & 3) == 0) {
        int r0 = rb * BM + wid * 16 + g_row;
        g_pm[chunk * NROWS + r0] = mA;
        g_ps[chunk * NROWS + r0] = sA;
        g_pm[chunk * NROWS + r0 + 8] = mB;
        g_ps[chunk * NROWS + r0 + 8] = sB;
    }

    // ---- last-CTA finalize (deterministic: fixed-order reduce by one CTA) ----
    __shared__ unsigned s_last;
    __shared__ float red[256];
    __threadfence();
    __syncthreads();
    if (tid == 0) {
        unsigned old = atomicAdd(&g_cnt, 1u);
        s_last = (old == GRID_F - 1) ? 1u : 0u;
        if (s_last) g_cnt = 0;   // reset for next graph replay
    }
    __syncthreads();
    if (!s_last) return;
    __threadfence();

    float acc = 0.f;
    for (int i = tid; i < NROWS; i += 256) {
        float M = -__int_as_float(0x7f800000), S = 0.f;
#pragma unroll
        for (int c = 0; c < NCHUNK; c++) {
            float m = g_pm[c * NROWS + i];
            float s = g_ps[c * NROWS + i];
            float nM = fmaxf(M, m);
            S = S * ex2(M - nM) + s * ex2(m - nM);
            M = nM;
        }
        float p = ex2(g_diag_arr[i] - M) / S;
        acc += -logf(p + 1e-5f);
    }
    red[tid] = acc;
    __syncthreads();
    for (int o = 128; o; o >>= 1) {
        if (tid < o) red[tid] += red[tid + o];
        __syncthreads();
    }
    if (tid == 0) out[0] = red[0] / (float)NROWS;
}

// ---------------------------------------------------------------------------
// Launch
// ---------------------------------------------------------------------------
extern "C" void kernel_launch(void* const* d_in, const int* in_sizes, int n_in,
                              void* d_out, int out_size) {
    (void)in_sizes; (void)n_in; (void)out_size;
    const float* q = (const float*)d_in[0];
    const float* g = (const float*)d_in[1];
    float* out = (float*)d_out;

    cudaFuncSetAttribute(fused_kernel, cudaFuncAttributeMaxDynamicSharedMemorySize, SMEM_TOTAL);

    prep_kernel<<<2048, 256>>>(q, g);
    fused_kernel<<<GRID_F, 256, SMEM_TOTAL>>>(q, out);
}